// round 8
// baseline (speedup 1.0000x reference)
#include <cuda_runtime.h>
#include <cuda_bf16.h>

#define NS 2000
#define NH 64
#define NB 1024
#define CH 125            // s-rows per chunk
#define NCH 16            // chunks (16*125 = 2000)
#define BG 4              // batch rows per CTA
#define NG (NB / BG)      // 256 b-groups

// Scratch for rel_encoded [S, H] (no cudaMalloc allowed)
__device__ float g_rel_enc[NS * NH];

// ---------------------------------------------------------------------------
// Kernel 1: rel_enc[s,:] = mask(s) * ( relu(rel[idx,s,:] @ W1^T + b1) @ W2^T + b2 )
// R2 shape: 500 blocks x 256 threads, 4 rows/block (measured fastest).
// ---------------------------------------------------------------------------
__global__ __launch_bounds__(256)
void mlp_kernel(const int* __restrict__ stock_idx,
                const float* __restrict__ rel,
                const float* __restrict__ W1,
                const float* __restrict__ b1,
                const float* __restrict__ W2,
                const float* __restrict__ b2)
{
    __shared__ float W1s[NH * 65];   // padded rows -> bank-conflict free
    __shared__ float W2s[NH * 65];
    __shared__ float rowbuf[4 * NH];
    __shared__ float hbuf[4 * NH];

    const int t = threadIdx.x;
    const int r = t >> 6;      // row-within-block 0..3
    const int j = t & 63;      // hidden index 0..63
    const int idx = *stock_idx;
    const int s = blockIdx.x * 4 + r;

    for (int i = t; i < NH * NH; i += 256) {
        W1s[(i >> 6) * 65 + (i & 63)] = W1[i];
        W2s[(i >> 6) * 65 + (i & 63)] = W2[i];
    }

    rowbuf[r * NH + j] = rel[(size_t)idx * NS * NH + (size_t)s * NH + j];
    __syncthreads();

    float acc = b1[j];
    #pragma unroll 16
    for (int k = 0; k < NH; k++)
        acc = fmaf(rowbuf[r * NH + k], W1s[j * 65 + k], acc);
    hbuf[r * NH + j] = fmaxf(acc, 0.0f);
    __syncthreads();

    float acc2 = b2[j];
    #pragma unroll 16
    for (int k = 0; k < NH; k++)
        acc2 = fmaf(hbuf[r * NH + k], W2s[j * 65 + k], acc2);

    if (s == idx) acc2 = 0.0f;   // exclude i == stock_idx
    g_rel_enc[s * NH + j] = acc2;
}

// ---------------------------------------------------------------------------
// Kernel 2: out[b,h] += sum_{s in chunk} enc[b,s,h] * rel_enc[s,h]
// CTA = (chunk c of 125 s-rows, group of BG=4 batch rows).
// rel chunk staged ONCE in smem (31.25KB) then reused for 4 batch rows:
// rel L2 traffic /4 -> LTS no longer the binding constraint.
// Consecutive bids share c (rel chunk L2-dedup) and spread over b (DRAM).
// ---------------------------------------------------------------------------
__global__ __launch_bounds__(256)
void reduce_kernel(const float4* __restrict__ enc,  // [B, S, 16] float4
                   float* __restrict__ out)         // [B, 64]
{
    __shared__ float4 rel_s[CH * 16];   // [125][16] float4 = 31.25 KB
    __shared__ float4 red[256];

    const int bid = blockIdx.x;
    const int c = bid >> 8;            // chunk 0..15  (consecutive bids: same c)
    const int g = bid & 255;           // b-group 0..255
    const int t = threadIdx.x;
    const int h16  = t & 15;           // float4 lane within hidden dim
    const int srow = t >> 4;           // 0..15

    // Stage rel chunk into shared (coalesced; L2-resident across CTAs)
    const float4* __restrict__ relg = ((const float4*)g_rel_enc) + c * CH * 16;
    for (int i = t; i < CH * 16; i += 256)
        rel_s[i] = relg[i];
    __syncthreads();

    #pragma unroll
    for (int bi = 0; bi < BG; bi++) {
        const int b = g * BG + bi;
        const float4* __restrict__ encB =
            enc + ((size_t)b * NS + (size_t)c * CH) * 16;

        float4 acc = make_float4(0.f, 0.f, 0.f, 0.f);

        #pragma unroll 4
        for (int s = srow; s < CH; s += 16) {
            const float4 e  = __ldcs(&encB[s * 16 + h16]);  // stream, evict-first
            const float4 rv = rel_s[s * 16 + h16];          // smem, conflict-free
            acc.x = fmaf(e.x, rv.x, acc.x);
            acc.y = fmaf(e.y, rv.y, acc.y);
            acc.z = fmaf(e.z, rv.z, acc.z);
            acc.w = fmaf(e.w, rv.w, acc.w);
        }

        red[t] = acc;
        __syncthreads();

        #pragma unroll
        for (int off = 128; off >= 16; off >>= 1) {
            if (t < off) {
                float4 a = red[t], bb = red[t + off];
                a.x += bb.x; a.y += bb.y; a.z += bb.z; a.w += bb.w;
                red[t] = a;
            }
            __syncthreads();
        }

        if (t < 64)
            atomicAdd(&out[b * NH + t], ((const float*)red)[t]);
        __syncthreads();   // red reused next b-pass
    }
}

// ---------------------------------------------------------------------------
// Inputs (metadata order):
//   d_in[0] stock_idx            int32   [1]
//   d_in[1] encoded_states       f32     [1024, 2000, 64]
//   d_in[2] relationship_matrix  f32     [2000, 2000, 64]
//   d_in[3] W1  f32 [64,64]   d_in[4] b1 f32 [64]
//   d_in[5] W2  f32 [64,64]   d_in[6] b2 f32 [64]
// Output: f32 [1024, 64]
// ---------------------------------------------------------------------------
extern "C" void kernel_launch(void* const* d_in, const int* in_sizes, int n_in,
                              void* d_out, int out_size)
{
    const int*   stock_idx = (const int*)  d_in[0];
    const float* enc       = (const float*)d_in[1];
    const float* rel       = (const float*)d_in[2];
    const float* W1        = (const float*)d_in[3];
    const float* b1        = (const float*)d_in[4];
    const float* W2        = (const float*)d_in[5];
    const float* b2        = (const float*)d_in[6];
    float* out = (float*)d_out;

    cudaMemsetAsync(out, 0, NB * NH * sizeof(float));
    mlp_kernel<<<NS / 4, 256>>>(stock_idx, rel, W1, b1, W2, b2);
    reduce_kernel<<<NCH * NG, 256>>>((const float4*)enc, out);
}

// round 10
// speedup vs baseline: 1.2210x; 1.2210x over previous
#include <cuda_runtime.h>
#include <cuda_bf16.h>

#define NS 2000
#define NH 64
#define NB 1024
#define CH 125            // s-rows per chunk
#define NCH 16            // chunks (16*125 = 2000)
#define BG 4              // batch rows per CTA (register-blocked, concurrent)
#define NG (NB / BG)      // 256 b-groups

// Scratch for rel_encoded [S, H] (no cudaMalloc allowed)
__device__ float g_rel_enc[NS * NH];

// ---------------------------------------------------------------------------
// Kernel 1: rel_enc[s,:] = mask(s) * ( relu(rel[idx,s,:] @ W1^T + b1) @ W2^T + b2 )
// 500 blocks x 256 threads, 4 rows/block (measured fastest shape).
// Also zero-initializes out for the reduce kernel's atomics.
// ---------------------------------------------------------------------------
__global__ __launch_bounds__(256)
void mlp_kernel(const int* __restrict__ stock_idx,
                const float* __restrict__ rel,
                const float* __restrict__ W1,
                const float* __restrict__ b1,
                const float* __restrict__ W2,
                const float* __restrict__ b2,
                float* __restrict__ out)
{
    __shared__ float W1s[NH * 65];   // padded rows -> bank-conflict free
    __shared__ float W2s[NH * 65];
    __shared__ float rowbuf[4 * NH];
    __shared__ float hbuf[4 * NH];

    const int t = threadIdx.x;
    const int r = t >> 6;      // row-within-block 0..3
    const int j = t & 63;      // hidden index 0..63
    const int idx = *stock_idx;
    const int s = blockIdx.x * 4 + r;

    // Zero the output (grid-stride over 1024*64 elements)
    for (int i = blockIdx.x * 256 + t; i < NB * NH; i += gridDim.x * 256)
        out[i] = 0.0f;

    for (int i = t; i < NH * NH; i += 256) {
        W1s[(i >> 6) * 65 + (i & 63)] = W1[i];
        W2s[(i >> 6) * 65 + (i & 63)] = W2[i];
    }

    rowbuf[r * NH + j] = rel[(size_t)idx * NS * NH + (size_t)s * NH + j];
    __syncthreads();

    float acc = b1[j];
    #pragma unroll 16
    for (int k = 0; k < NH; k++)
        acc = fmaf(rowbuf[r * NH + k], W1s[j * 65 + k], acc);
    hbuf[r * NH + j] = fmaxf(acc, 0.0f);
    __syncthreads();

    float acc2 = b2[j];
    #pragma unroll 16
    for (int k = 0; k < NH; k++)
        acc2 = fmaf(hbuf[r * NH + k], W2s[j * 65 + k], acc2);

    if (s == idx) acc2 = 0.0f;   // exclude i == stock_idx
    g_rel_enc[s * NH + j] = acc2;
}

// ---------------------------------------------------------------------------
// Kernel 2: out[b,h] += sum_{s in chunk} enc[b,s,h] * rel_enc[s,h]
// CTA = (chunk c of 125 s-rows, group of BG=4 CONCURRENT batch rows).
// rel chunk staged once in smem; streaming loop has ZERO barriers and issues
// 4 independent LDG.128 per thread-iteration (4 register accumulators).
// Tree reductions run exactly once, after all loads.
// ---------------------------------------------------------------------------
__global__ __launch_bounds__(256)
void reduce_kernel(const float4* __restrict__ enc,  // [B, S, 16] float4
                   float* __restrict__ out)         // [B, 64]
{
    __shared__ float4 rel_s[CH * 16];   // 31.25 KB
    __shared__ float4 red[256];

    const int bid = blockIdx.x;
    const int c = bid >> 8;            // chunk 0..15 (256 consecutive bids share c)
    const int g = bid & 255;           // b-group 0..255
    const int t = threadIdx.x;
    const int h16  = t & 15;           // float4 lane within hidden dim
    const int srow = t >> 4;           // 0..15

    // Stage rel chunk into shared (coalesced; L2-resident across CTAs)
    const float4* __restrict__ relg = ((const float4*)g_rel_enc) + c * CH * 16;
    for (int i = t; i < CH * 16; i += 256)
        rel_s[i] = __ldg(&relg[i]);
    __syncthreads();

    const size_t b0 = (size_t)g * BG;
    const float4* __restrict__ encB = enc + (b0 * NS + (size_t)c * CH) * 16;
    const int strideB = NS * 16;       // float4 stride between batch rows

    float4 a0 = make_float4(0.f,0.f,0.f,0.f);
    float4 a1 = a0, a2 = a0, a3 = a0;

    #pragma unroll 2
    for (int s = srow; s < CH; s += 16) {
        const int o = s * 16 + h16;
        const float4 rv = rel_s[o];
        const float4 e0 = __ldcs(&encB[o]);
        const float4 e1 = __ldcs(&encB[o + strideB]);
        const float4 e2 = __ldcs(&encB[o + 2 * strideB]);
        const float4 e3 = __ldcs(&encB[o + 3 * strideB]);
        a0.x = fmaf(e0.x, rv.x, a0.x); a0.y = fmaf(e0.y, rv.y, a0.y);
        a0.z = fmaf(e0.z, rv.z, a0.z); a0.w = fmaf(e0.w, rv.w, a0.w);
        a1.x = fmaf(e1.x, rv.x, a1.x); a1.y = fmaf(e1.y, rv.y, a1.y);
        a1.z = fmaf(e1.z, rv.z, a1.z); a1.w = fmaf(e1.w, rv.w, a1.w);
        a2.x = fmaf(e2.x, rv.x, a2.x); a2.y = fmaf(e2.y, rv.y, a2.y);
        a2.z = fmaf(e2.z, rv.z, a2.z); a2.w = fmaf(e2.w, rv.w, a2.w);
        a3.x = fmaf(e3.x, rv.x, a3.x); a3.y = fmaf(e3.y, rv.y, a3.y);
        a3.z = fmaf(e3.z, rv.z, a3.z); a3.w = fmaf(e3.w, rv.w, a3.w);
    }

    // One reduction pass per batch row, AFTER all streaming is done.
    float4 accs[BG] = {a0, a1, a2, a3};
    #pragma unroll
    for (int bi = 0; bi < BG; bi++) {
        red[t] = accs[bi];
        __syncthreads();
        #pragma unroll
        for (int off = 128; off >= 16; off >>= 1) {
            if (t < off) {
                float4 a = red[t], bb = red[t + off];
                a.x += bb.x; a.y += bb.y; a.z += bb.z; a.w += bb.w;
                red[t] = a;
            }
            __syncthreads();
        }
        if (t < 64)
            atomicAdd(&out[(b0 + bi) * NH + t], ((const float*)red)[t]);
        __syncthreads();
    }
}

// ---------------------------------------------------------------------------
// Inputs (metadata order):
//   d_in[0] stock_idx            int32   [1]
//   d_in[1] encoded_states       f32     [1024, 2000, 64]
//   d_in[2] relationship_matrix  f32     [2000, 2000, 64]
//   d_in[3] W1  f32 [64,64]   d_in[4] b1 f32 [64]
//   d_in[5] W2  f32 [64,64]   d_in[6] b2 f32 [64]
// Output: f32 [1024, 64]
// ---------------------------------------------------------------------------
extern "C" void kernel_launch(void* const* d_in, const int* in_sizes, int n_in,
                              void* d_out, int out_size)
{
    const int*   stock_idx = (const int*)  d_in[0];
    const float* enc       = (const float*)d_in[1];
    const float* rel       = (const float*)d_in[2];
    const float* W1        = (const float*)d_in[3];
    const float* b1        = (const float*)d_in[4];
    const float* W2        = (const float*)d_in[5];
    const float* b2        = (const float*)d_in[6];
    float* out = (float*)d_out;

    mlp_kernel<<<NS / 4, 256>>>(stock_idx, rel, W1, b1, W2, b2, out);
    reduce_kernel<<<NCH * NG, 256>>>((const float4*)enc, out);
}

// round 11
// speedup vs baseline: 1.3657x; 1.1185x over previous
#include <cuda_runtime.h>
#include <cuda_bf16.h>

#define NS 2000
#define NH 64
#define NB 1024
#define NQ 4              // s-dimension split per batch pair
#define SQ (NS / NQ)      // 500 s-rows per tile
#define BG 2              // batch rows per CTA (register-blocked, concurrent)

// Scratch for rel_encoded [S, H] (no cudaMalloc allowed)
__device__ float g_rel_enc[NS * NH];

// ---------------------------------------------------------------------------
// Kernel 1: rel_enc[s,:] = mask(s) * ( relu(rel[idx,s,:] @ W1^T + b1) @ W2^T + b2 )
// 500 blocks x 256 threads, 4 rows/block (measured fastest shape).
// Also zero-initializes out for the reduce kernel's atomics.
// ---------------------------------------------------------------------------
__global__ __launch_bounds__(256)
void mlp_kernel(const int* __restrict__ stock_idx,
                const float* __restrict__ rel,
                const float* __restrict__ W1,
                const float* __restrict__ b1,
                const float* __restrict__ W2,
                const float* __restrict__ b2,
                float* __restrict__ out)
{
    __shared__ float W1s[NH * 65];   // padded rows -> bank-conflict free
    __shared__ float W2s[NH * 65];
    __shared__ float rowbuf[4 * NH];
    __shared__ float hbuf[4 * NH];

    const int t = threadIdx.x;
    const int r = t >> 6;      // row-within-block 0..3
    const int j = t & 63;      // hidden index 0..63
    const int idx = *stock_idx;
    const int s = blockIdx.x * 4 + r;

    // Zero the output (grid-stride over 1024*64 elements)
    for (int i = blockIdx.x * 256 + t; i < NB * NH; i += gridDim.x * 256)
        out[i] = 0.0f;

    for (int i = t; i < NH * NH; i += 256) {
        W1s[(i >> 6) * 65 + (i & 63)] = W1[i];
        W2s[(i >> 6) * 65 + (i & 63)] = W2[i];
    }

    rowbuf[r * NH + j] = rel[(size_t)idx * NS * NH + (size_t)s * NH + j];
    __syncthreads();

    float acc = b1[j];
    #pragma unroll 16
    for (int k = 0; k < NH; k++)
        acc = fmaf(rowbuf[r * NH + k], W1s[j * 65 + k], acc);
    hbuf[r * NH + j] = fmaxf(acc, 0.0f);
    __syncthreads();

    float acc2 = b2[j];
    #pragma unroll 16
    for (int k = 0; k < NH; k++)
        acc2 = fmaf(hbuf[r * NH + k], W2s[j * 65 + k], acc2);

    if (s == idx) acc2 = 0.0f;   // exclude i == stock_idx
    g_rel_enc[s * NH + j] = acc2;
}

// ---------------------------------------------------------------------------
// Kernel 2: out[b,h] += sum_{s in quarter} enc[b,s,h] * rel_enc[s,h]
// Flat R2 structure, but each CTA processes BG=2 CONCURRENT batch rows:
// one rel L2 read feeds two enc streams -> rel LTS traffic halved, only
// ~8 extra registers. No smem in the hot loop, no barriers in the hot loop.
// grid = NQ * NB/2 = 2048 tiles.
// ---------------------------------------------------------------------------
__global__ __launch_bounds__(256)
void reduce_kernel(const float4* __restrict__ enc,  // [B, S, 16] float4
                   float* __restrict__ out)         // [B, 64]
{
    const int tile = blockIdx.x;
    const int p = tile >> 2;           // batch pair 0..511
    const int q = tile & 3;            // s-quarter
    const int t = threadIdx.x;
    const int h16  = t & 15;           // float4 lane within hidden dim
    const int srow = t >> 4;           // 0..15

    const size_t b0 = (size_t)p * BG;
    const float4* __restrict__ enc0 = enc + (b0 * NS + (size_t)q * SQ) * 16;
    const int strideB = NS * 16;       // float4 stride between batch rows
    const float4* __restrict__ rel4 =
        ((const float4*)g_rel_enc) + (size_t)q * SQ * 16;

    float4 a0 = make_float4(0.f, 0.f, 0.f, 0.f);
    float4 a1 = a0;

    #pragma unroll 4
    for (int s = srow; s < SQ; s += 16) {
        const int o = s * 16 + h16;
        const float4 rv = rel4[o];                 // L2-resident
        const float4 e0 = __ldcs(&enc0[o]);        // stream, evict-first
        const float4 e1 = __ldcs(&enc0[o + strideB]);
        a0.x = fmaf(e0.x, rv.x, a0.x); a0.y = fmaf(e0.y, rv.y, a0.y);
        a0.z = fmaf(e0.z, rv.z, a0.z); a0.w = fmaf(e0.w, rv.w, a0.w);
        a1.x = fmaf(e1.x, rv.x, a1.x); a1.y = fmaf(e1.y, rv.y, a1.y);
        a1.z = fmaf(e1.z, rv.z, a1.z); a1.w = fmaf(e1.w, rv.w, a1.w);
    }

    __shared__ float4 red[256];
    float4 accs[BG] = {a0, a1};

    #pragma unroll
    for (int bi = 0; bi < BG; bi++) {
        red[t] = accs[bi];
        __syncthreads();
        #pragma unroll
        for (int off = 128; off >= 16; off >>= 1) {
            if (t < off) {
                float4 a = red[t], bb = red[t + off];
                a.x += bb.x; a.y += bb.y; a.z += bb.z; a.w += bb.w;
                red[t] = a;
            }
            __syncthreads();
        }
        if (t < 64)
            atomicAdd(&out[(b0 + bi) * NH + t], ((const float*)red)[t]);
        __syncthreads();
    }
}

// ---------------------------------------------------------------------------
// Inputs (metadata order):
//   d_in[0] stock_idx            int32   [1]
//   d_in[1] encoded_states       f32     [1024, 2000, 64]
//   d_in[2] relationship_matrix  f32     [2000, 2000, 64]
//   d_in[3] W1  f32 [64,64]   d_in[4] b1 f32 [64]
//   d_in[5] W2  f32 [64,64]   d_in[6] b2 f32 [64]
// Output: f32 [1024, 64]
// ---------------------------------------------------------------------------
extern "C" void kernel_launch(void* const* d_in, const int* in_sizes, int n_in,
                              void* d_out, int out_size)
{
    const int*   stock_idx = (const int*)  d_in[0];
    const float* enc       = (const float*)d_in[1];
    const float* rel       = (const float*)d_in[2];
    const float* W1        = (const float*)d_in[3];
    const float* b1        = (const float*)d_in[4];
    const float* W2        = (const float*)d_in[5];
    const float* b2        = (const float*)d_in[6];
    float* out = (float*)d_out;

    mlp_kernel<<<NS / 4, 256>>>(stock_idx, rel, W1, b1, W2, b2, out);
    reduce_kernel<<<(NB / BG) * NQ, 256>>>((const float4*)enc, out);
}